// round 1
// baseline (speedup 1.0000x reference)
#include <cuda_runtime.h>
#include <cstdint>
#include <math.h>

#define N_  32
#define T_  1024
#define D_  512
#define H_  512
#define G4  2048

#define NB  128     // persistent CTAs (<= 148 SMs, all co-resident)
#define NTH 256

// ---------------- device scratch (sanctioned __device__ globals) ----------------
__device__ float g_xw[(size_t)N_ * T_ * G4];      // 256 MB: x@Wx + b, [(n*T+t)][2048]
__device__ float g_hbuf[2][H_][N_];               // double-buffered h, [k][n]
__device__ unsigned int g_count = 0;
__device__ volatile unsigned int g_gen = 0;

// ---------------- Phase 1: xw = x @ Wx + b  (32768 x 2048 x 512 SGEMM) ----------
__global__ __launch_bounds__(256, 2) void gemm_xw_kernel(const float* __restrict__ x,
                                                         const float* __restrict__ Wx,
                                                         const float* __restrict__ bias)
{
    __shared__ float As[8][128];   // A tile transposed: As[k][m]
    __shared__ float Bs[8][128];   // B tile: Bs[k][n]
    const int tid = threadIdx.x;
    const int bm = blockIdx.y, bn = blockIdx.x;
    const int tx = tid & 15, ty = tid >> 4;          // 16x16 thread grid, 8x8 microtile
    const int a_row = tid >> 1, a_k = (tid & 1) << 2;
    const int b_row = tid >> 5, b_col = (tid & 31) << 2;

    const float* xA = x + (size_t)(bm * 128 + a_row) * D_ + a_k;
    const float* wB = Wx + (size_t)b_row * G4 + bn * 128 + b_col;

    float acc[8][8];
#pragma unroll
    for (int i = 0; i < 8; i++)
#pragma unroll
        for (int j = 0; j < 8; j++) acc[i][j] = 0.f;

    for (int k0 = 0; k0 < D_; k0 += 8) {
        float4 av = *(const float4*)(xA + k0);
        float4 bv = *(const float4*)(wB + (size_t)k0 * G4);
        __syncthreads();
        As[a_k + 0][a_row] = av.x;
        As[a_k + 1][a_row] = av.y;
        As[a_k + 2][a_row] = av.z;
        As[a_k + 3][a_row] = av.w;
        *(float4*)&Bs[b_row][b_col] = bv;
        __syncthreads();
#pragma unroll
        for (int kk = 0; kk < 8; kk++) {
            float a0[8], b0[8];
            *(float4*)(a0)     = *(const float4*)&As[kk][ty * 8];
            *(float4*)(a0 + 4) = *(const float4*)&As[kk][ty * 8 + 4];
            *(float4*)(b0)     = *(const float4*)&Bs[kk][tx * 8];
            *(float4*)(b0 + 4) = *(const float4*)&Bs[kk][tx * 8 + 4];
#pragma unroll
            for (int i = 0; i < 8; i++)
#pragma unroll
                for (int j = 0; j < 8; j++)
                    acc[i][j] = fmaf(a0[i], b0[j], acc[i][j]);
        }
    }

    float bb[8];
    *(float4*)(bb)     = *(const float4*)(bias + bn * 128 + tx * 8);
    *(float4*)(bb + 4) = *(const float4*)(bias + bn * 128 + tx * 8 + 4);
#pragma unroll
    for (int i = 0; i < 8; i++) {
        size_t row = (size_t)(bm * 128 + ty * 8 + i);
        float4 v0 = make_float4(acc[i][0] + bb[0], acc[i][1] + bb[1],
                                acc[i][2] + bb[2], acc[i][3] + bb[3]);
        float4 v1 = make_float4(acc[i][4] + bb[4], acc[i][5] + bb[5],
                                acc[i][6] + bb[6], acc[i][7] + bb[7]);
        *(float4*)(g_xw + row * G4 + bn * 128 + tx * 8)     = v0;
        *(float4*)(g_xw + row * G4 + bn * 128 + tx * 8 + 4) = v1;
    }
}

// ---------------- Phase 2: persistent recurrent kernel --------------------------
__device__ __forceinline__ void gridbar()
{
    __syncthreads();
    if (threadIdx.x == 0) {
        __threadfence();                       // flush my writes (also CCTL.IVALL)
        unsigned gen = g_gen;
        if (atomicAdd(&g_count, 1) == NB - 1) {
            atomicExch(&g_count, 0);
            __threadfence();
            g_gen = gen + 1;
        } else {
            while (g_gen == gen) { }
            __threadfence();                   // acquire: invalidate L1 before reads
        }
    }
    __syncthreads();
}

extern __shared__ float smem_dyn[];

__global__ __launch_bounds__(NTH, 1) void lstm_rec_kernel(const float* __restrict__ h0,
                                                          const float* __restrict__ Wh,
                                                          float* __restrict__ out)
{
    // smem layout (floats): Whs[512][16] | hs[512][32] | ap[8][32][16] | af[32][16] | cs[128]
    float* Whs = smem_dyn;               // 8192
    float* hs  = Whs + 512 * 16;         // 16384
    float* ap  = hs + 512 * 32;          // 4096
    float* af  = ap + 8 * 32 * 16;       // 512
    float* cs  = af + 32 * 16;           // 128

    const int b   = blockIdx.x;
    const int tid = threadIdx.x;
    const int j0  = b * 4;               // this CTA's 4 h-columns: j0..j0+3

    // Load weight slice: Whs[k][gate*4+jj] = Wh[k][gate*512 + j0 + jj]
    for (int idx = tid; idx < 512 * 16; idx += NTH) {
        int k = idx >> 4, c = idx & 15;
        int gate = c >> 2, jj = c & 3;
        Whs[idx] = Wh[(size_t)k * G4 + gate * H_ + j0 + jj];
    }
    if (tid < 128) {
        cs[tid] = 0.f;                   // c0 = 0,  cs[n*4+jj]
        int n = tid >> 2, jj = tid & 3;
        g_hbuf[0][j0 + jj][n] = h0[(size_t)n * H_ + j0 + jj];
    }
    gridbar();

    // compute mapping: warp = K-group (K slice of 64), lanes tile 4n x 4c over 32x16
    const int grp  = tid >> 5;           // 0..7
    const int lane = tid & 31;
    const int n0   = (lane >> 2) * 4;    // 0,4,...,28
    const int c0   = (lane & 3) * 4;     // 0,4,8,12 (one gate per lane-column)
    const int kbeg = grp * 64;

    for (int t = 0; t < T_; t++) {
        // stage h (fp32, [k][n]) into smem — coalesced LDG.128, conflict-free STS.128
        const float* hsrc = &g_hbuf[t & 1][0][0];
#pragma unroll
        for (int idx = tid * 4; idx < H_ * N_; idx += NTH * 4) {
            float4 v = __ldcg((const float4*)(hsrc + idx));
            *(float4*)(hs + idx) = v;
        }
        __syncthreads();

        // partial GEMM: acc[4n][4c] over this warp's K slice
        float acc[4][4];
#pragma unroll
        for (int i = 0; i < 4; i++)
#pragma unroll
            for (int c = 0; c < 4; c++) acc[i][c] = 0.f;

#pragma unroll 8
        for (int k = 0; k < 64; k++) {
            float4 hv = *(const float4*)(hs + (kbeg + k) * 32 + n0);
            float4 wv = *(const float4*)(Whs + (kbeg + k) * 16 + c0);
            float h4[4] = {hv.x, hv.y, hv.z, hv.w};
            float w4[4] = {wv.x, wv.y, wv.z, wv.w};
#pragma unroll
            for (int i = 0; i < 4; i++)
#pragma unroll
                for (int c = 0; c < 4; c++)
                    acc[i][c] = fmaf(h4[i], w4[c], acc[i][c]);
        }
#pragma unroll
        for (int i = 0; i < 4; i++)
            *(float4*)(ap + ((grp * 32) + n0 + i) * 16 + c0) =
                make_float4(acc[i][0], acc[i][1], acc[i][2], acc[i][3]);
        __syncthreads();

        // reduce 8 partials + add xw (precomputed x@Wx+b)
        if (tid < 128) {
            int n = tid >> 2, q = tid & 3;   // q = gate
            const float* xwp = g_xw + ((size_t)n * T_ + t) * G4 + q * H_ + j0;
            float4 s = __ldcg((const float4*)xwp);
#pragma unroll
            for (int g = 0; g < 8; g++) {
                float4 p = *(const float4*)(ap + (g * 32 + n) * 16 + q * 4);
                s.x += p.x; s.y += p.y; s.z += p.z; s.w += p.w;
            }
            *(float4*)(af + n * 16 + q * 4) = s;
        }
        __syncthreads();

        // gates + state update; write h_next to the other buffer and to out
        if (tid < 128) {
            int n = tid >> 2, jj = tid & 3;
            float ai = af[n * 16 + 0  + jj];
            float afv = af[n * 16 + 4  + jj];
            float ao = af[n * 16 + 8  + jj];
            float ag = af[n * 16 + 12 + jj];
            float ig = 1.f / (1.f + expf(-ai));
            float fg = 1.f / (1.f + expf(-afv));
            float og = 1.f / (1.f + expf(-ao));
            float gg = tanhf(ag);
            float cn = fg * cs[tid] + ig * gg;
            cs[tid] = cn;
            float hn = og * tanhf(cn);
            g_hbuf[(t + 1) & 1][j0 + jj][n] = hn;
            out[((size_t)n * T_ + t) * H_ + j0 + jj] = hn;
        }
        gridbar();
    }
}

// ---------------- launch ---------------------------------------------------------
extern "C" void kernel_launch(void* const* d_in, const int* in_sizes, int n_in,
                              void* d_out, int out_size)
{
    const float* x    = (const float*)d_in[0];
    const float* h0   = (const float*)d_in[1];
    const float* Wx   = (const float*)d_in[2];
    const float* Wh   = (const float*)d_in[3];
    const float* bias = (const float*)d_in[4];
    float* out = (float*)d_out;

    dim3 g1(G4 / 128, (N_ * T_) / 128);
    gemm_xw_kernel<<<g1, 256>>>(x, Wx, bias);

    const int shmem = (512 * 16 + 512 * 32 + 8 * 32 * 16 + 32 * 16 + 128) * (int)sizeof(float);
    cudaFuncSetAttribute(lstm_rec_kernel, cudaFuncAttributeMaxDynamicSharedMemorySize, shmem);
    lstm_rec_kernel<<<NB, NTH, shmem>>>(h0, Wh, out);
}

// round 2
// speedup vs baseline: 1.0305x; 1.0305x over previous
#include <cuda_runtime.h>
#include <cstdint>
#include <math.h>

#define N_  32
#define T_  1024
#define D_  512
#define H_  512
#define G4  2048

#define NB  128     // persistent CTAs (<= 148 SMs, all co-resident)
#define NTH 256
#define HSTR 516    // padded k-stride for smem tiles (bank stagger)

typedef unsigned long long ull;

// ---------------- packed f32x2 helpers ------------------------------------------
__device__ __forceinline__ void fma2(ull& d, const ull a, const ull b) {
    asm("fma.rn.f32x2 %0, %1, %2, %0;" : "+l"(d) : "l"(a), "l"(b));
}
__device__ __forceinline__ void add2(ull& d, const ull a) {
    asm("add.rn.f32x2 %0, %0, %1;" : "+l"(d) : "l"(a));
}
__device__ __forceinline__ ull bcast2(float x) {
    ull r; asm("mov.b64 %0, {%1, %1};" : "=l"(r) : "f"(x)); return r;
}
__device__ __forceinline__ float hsum2(ull a) {
    float lo, hi; asm("mov.b64 {%0, %1}, %2;" : "=f"(lo), "=f"(hi) : "l"(a));
    return lo + hi;
}

// ---------------- device scratch -------------------------------------------------
__device__ float g_xw[(size_t)N_ * T_ * G4];      // 256 MB: x@Wx + b, [(n*T+t)][2048]
__device__ float g_hbuf[2][N_][H_];               // double-buffered h, [n][k]
__device__ unsigned int g_count = 0;
__device__ volatile unsigned int g_gen = 0;

// ---------------- Phase 1: xw = x @ Wx + b  (32768 x 2048 x 512, FFMA2) ----------
__global__ __launch_bounds__(256, 2) void gemm_xw_kernel(const float* __restrict__ x,
                                                         const float* __restrict__ Wx,
                                                         const float* __restrict__ bias)
{
    __shared__ float As[8][128];   // A tile transposed: As[k][m]
    __shared__ float Bs[8][128];   // B tile: Bs[k][n]
    const int tid = threadIdx.x;
    const int bm = blockIdx.y, bn = blockIdx.x;
    const int tx = tid & 15, ty = tid >> 4;          // 16x16 thread grid, 8x8 microtile
    const int a_row = tid >> 1, a_k = (tid & 1) << 2;
    const int b_row = tid >> 5, b_col = (tid & 31) << 2;

    const float* xA = x + (size_t)(bm * 128 + a_row) * D_ + a_k;
    const float* wB = Wx + (size_t)b_row * G4 + bn * 128 + b_col;

    ull accp[8][4];                // acc[i][j pair], j packed in f32x2
#pragma unroll
    for (int i = 0; i < 8; i++)
#pragma unroll
        for (int j = 0; j < 4; j++) accp[i][j] = 0ULL;

    for (int k0 = 0; k0 < D_; k0 += 8) {
        float4 av = *(const float4*)(xA + k0);
        float4 bv = *(const float4*)(wB + (size_t)k0 * G4);
        __syncthreads();
        As[a_k + 0][a_row] = av.x;
        As[a_k + 1][a_row] = av.y;
        As[a_k + 2][a_row] = av.z;
        As[a_k + 3][a_row] = av.w;
        *(float4*)&Bs[b_row][b_col] = bv;
        __syncthreads();
#pragma unroll
        for (int kk = 0; kk < 8; kk++) {
            float a0[8];
            *(float4*)(a0)     = *(const float4*)&As[kk][ty * 8];
            *(float4*)(a0 + 4) = *(const float4*)&As[kk][ty * 8 + 4];
            ulonglong2 q0 = *(const ulonglong2*)&Bs[kk][tx * 8];
            ulonglong2 q1 = *(const ulonglong2*)&Bs[kk][tx * 8 + 4];
            ull b2[4] = {q0.x, q0.y, q1.x, q1.y};
            ull a2[8];
#pragma unroll
            for (int i = 0; i < 8; i++) a2[i] = bcast2(a0[i]);
#pragma unroll
            for (int i = 0; i < 8; i++)
#pragma unroll
                for (int j = 0; j < 4; j++)
                    fma2(accp[i][j], a2[i], b2[j]);
        }
    }

    ulonglong2 bq0 = *(const ulonglong2*)(bias + bn * 128 + tx * 8);
    ulonglong2 bq1 = *(const ulonglong2*)(bias + bn * 128 + tx * 8 + 4);
    ull bb2[4] = {bq0.x, bq0.y, bq1.x, bq1.y};
#pragma unroll
    for (int i = 0; i < 8; i++) {
#pragma unroll
        for (int j = 0; j < 4; j++) add2(accp[i][j], bb2[j]);
        size_t row = (size_t)(bm * 128 + ty * 8 + i);
        ulonglong2 s0, s1;
        s0.x = accp[i][0]; s0.y = accp[i][1];
        s1.x = accp[i][2]; s1.y = accp[i][3];
        *(ulonglong2*)(g_xw + row * G4 + bn * 128 + tx * 8)     = s0;
        *(ulonglong2*)(g_xw + row * G4 + bn * 128 + tx * 8 + 4) = s1;
    }
}

// ---------------- Phase 2: persistent recurrent kernel ---------------------------
__device__ __forceinline__ void gridbar()
{
    __syncthreads();
    if (threadIdx.x == 0) {
        __threadfence();                       // release: flush my writes
        unsigned gen = g_gen;
        if (atomicAdd(&g_count, 1) == NB - 1) {
            atomicExch(&g_count, 0);
            __threadfence();
            g_gen = gen + 1;
        } else {
            while (g_gen == gen) { }
            __threadfence();                   // acquire
        }
    }
    __syncthreads();
}

extern __shared__ float smem_dyn[];

__global__ __launch_bounds__(NTH, 1) void lstm_rec_kernel(const float* __restrict__ h0,
                                                          const float* __restrict__ Wh,
                                                          float* __restrict__ out)
{
    // smem layout (floats): Whs[16][HSTR] | hs[32][HSTR] | ap[8][32][16] | af[32][16] | cs[128]
    float* Whs = smem_dyn;                 // 16 * 516
    float* hs  = Whs + 16 * HSTR;          // 32 * 516
    float* ap  = hs + 32 * HSTR;           // 4096
    float* af  = ap + 8 * 32 * 16;         // 512
    float* cs  = af + 32 * 16;             // 128

    const int b   = blockIdx.x;
    const int tid = threadIdx.x;
    const int j0  = b * 4;                 // this CTA's 4 h-columns: j0..j0+3

    // Load weight slice transposed: Whs[c][k] = Wh[k][gate*512 + j0 + jj], c = gate*4+jj
    for (int idx = tid; idx < 16 * 512; idx += NTH) {
        int k = idx >> 4, c = idx & 15;
        int gate = c >> 2, jj = c & 3;
        Whs[c * HSTR + k] = Wh[(size_t)k * G4 + gate * H_ + j0 + jj];
    }
    if (tid < 128) {
        cs[tid] = 0.f;                     // c0 = 0,  cs[n*4+jj]
        int n = tid >> 2, jj = tid & 3;
        g_hbuf[0][n][j0 + jj] = h0[(size_t)n * H_ + j0 + jj];
    }
    gridbar();

    // mapping: warp = K-group (slice of 64 k's); lane covers 4n x 4c
    const int grp  = tid >> 5;             // 0..7
    const int lane = tid & 31;
    const int kbeg = grp * 64;
    const int n0   = lane >> 2;            // rows n0, n0+8, n0+16, n0+24
    const int c0r  = lane & 3;             // cols c0r, c0r+4, c0r+8, c0r+12 (jj=c0r, gate=cm)
    const int sub  = lane >> 3;            // staging: row within group of 4
    const int qo   = (lane & 7) * 8;       // staging: float offset within 64-float slice

    for (int t = 0; t < T_; t++) {
        // prefetch this thread's xw row early (hidden behind the GEMM)
        float4 xwv = make_float4(0.f, 0.f, 0.f, 0.f);
        if (tid < 128) {
            int n = tid >> 2, q = tid & 3;
            xwv = __ldcg((const float4*)(g_xw + ((size_t)n * T_ + t) * G4 + q * H_ + j0));
        }

        // stage this warp's own K-slice of h ([n][k] layout), coalesced 256B rows
        const float* hb = &g_hbuf[t & 1][0][0];
#pragma unroll
        for (int r = 0; r < 8; r++) {
            int row = r * 4 + sub;
            const float* src = hb + row * 512 + kbeg + qo;
            float4 va = __ldcg((const float4*)src);
            float4 vb = __ldcg((const float4*)(src + 4));
            float* dst = hs + row * HSTR + kbeg + qo;
            *(float4*)dst = va;
            *(float4*)(dst + 4) = vb;
        }
        __syncwarp();

        // partial GEMM over own K slice; K packed into f32x2 halves (even/odd sums)
        ull acc[4][4];
#pragma unroll
        for (int m = 0; m < 4; m++)
#pragma unroll
            for (int cm = 0; cm < 4; cm++) acc[m][cm] = 0ULL;

        const float* hpb = hs + kbeg;
        const float* wpb = Whs + kbeg;
#pragma unroll 4
        for (int kq = 0; kq < 16; kq++) {
            ulonglong2 hv[4], wv[4];
#pragma unroll
            for (int m = 0; m < 4; m++)
                hv[m] = *(const ulonglong2*)(hpb + (n0 + 8 * m) * HSTR + kq * 4);
#pragma unroll
            for (int cm = 0; cm < 4; cm++)
                wv[cm] = *(const ulonglong2*)(wpb + (cm * 4 + c0r) * HSTR + kq * 4);
#pragma unroll
            for (int m = 0; m < 4; m++)
#pragma unroll
                for (int cm = 0; cm < 4; cm++) {
                    fma2(acc[m][cm], hv[m].x, wv[cm].x);
                    fma2(acc[m][cm], hv[m].y, wv[cm].y);
                }
        }
#pragma unroll
        for (int m = 0; m < 4; m++)
#pragma unroll
            for (int cm = 0; cm < 4; cm++)
                ap[(grp * 32 + n0 + 8 * m) * 16 + cm * 4 + c0r] = hsum2(acc[m][cm]);
        __syncthreads();

        // reduce 8 partials + xw (prefetched)
        if (tid < 128) {
            int n = tid >> 2, q = tid & 3;
            float4 s = xwv;
#pragma unroll
            for (int g = 0; g < 8; g++) {
                float4 p = *(const float4*)(ap + (g * 32 + n) * 16 + q * 4);
                s.x += p.x; s.y += p.y; s.z += p.z; s.w += p.w;
            }
            *(float4*)(af + n * 16 + q * 4) = s;
        }
        __syncthreads();

        // gates + state update
        if (tid < 128) {
            int n = tid >> 2, jj = tid & 3;
            float ai  = af[n * 16 + 0  + jj];
            float afv = af[n * 16 + 4  + jj];
            float ao  = af[n * 16 + 8  + jj];
            float ag  = af[n * 16 + 12 + jj];
            float ig = 1.f / (1.f + expf(-ai));
            float fg = 1.f / (1.f + expf(-afv));
            float og = 1.f / (1.f + expf(-ao));
            float gg = tanhf(ag);
            float cn = fg * cs[tid] + ig * gg;
            cs[tid] = cn;
            float hn = og * tanhf(cn);
            g_hbuf[(t + 1) & 1][n][j0 + jj] = hn;
            out[((size_t)n * T_ + t) * H_ + j0 + jj] = hn;
        }
        gridbar();
    }
}

// ---------------- launch ----------------------------------------------------------
extern "C" void kernel_launch(void* const* d_in, const int* in_sizes, int n_in,
                              void* d_out, int out_size)
{
    const float* x    = (const float*)d_in[0];
    const float* h0   = (const float*)d_in[1];
    const float* Wx   = (const float*)d_in[2];
    const float* Wh   = (const float*)d_in[3];
    const float* bias = (const float*)d_in[4];
    float* out = (float*)d_out;

    dim3 g1(G4 / 128, (N_ * T_) / 128);
    gemm_xw_kernel<<<g1, 256>>>(x, Wx, bias);

    const int shmem = (16 * HSTR + 32 * HSTR + 8 * 32 * 16 + 32 * 16 + 128) * (int)sizeof(float);
    cudaFuncSetAttribute(lstm_rec_kernel, cudaFuncAttributeMaxDynamicSharedMemorySize, shmem);
    lstm_rec_kernel<<<NB, NTH, shmem>>>(h0, Wh, out);
}